// round 1
// baseline (speedup 1.0000x reference)
#include <cuda_runtime.h>

// Problem constants (fixed by the reference)
#define NPOINTS     500000
#define NWAVE       128
#define NOFFSETS    50

#define TPB         128     // one thread per wavelength
#define NBLOCKS     1184    // 8 blocks per SM on 148-SM GB300
#define TILE        128     // points per smem tile

#define TWO_PI      6.283185307179586f

// Deterministic two-stage reduction scratch (no atomics -> bitwise deterministic).
__device__ float g_partialC[NBLOCKS * NWAVE];
__device__ float g_partialS[NBLOCKS * NWAVE];

__global__ __launch_bounds__(TPB, 8)
void accum_kernel(const float2* __restrict__ xy,
                  const float*  __restrict__ tid,
                  const float*  __restrict__ center,
                  const float*  __restrict__ wavelength)
{
    __shared__ float sdist[TILE];

    const int w  = threadIdx.x;           // this thread's wavelength column
    const float kw = TWO_PI / wavelength[w];
    const float cx = center[0];
    const float cy = center[1];

    float accC = 0.0f;
    float accS = 0.0f;

    for (int base = blockIdx.x * TILE; base < NPOINTS; base += gridDim.x * TILE) {
        // Phase A: cooperatively compute dist for this tile of points.
        const int p = base + threadIdx.x;
        if (p < NPOINTS) {
            const float2 v = xy[p];
            const float dx = v.x - cx;
            const float dy = v.y - cy;
            sdist[threadIdx.x] = sqrtf(fmaf(dx, dx, dy * dy));
        }
        __syncthreads();

        // Phase B: each thread sweeps the tile's points for its wavelength.
        const int cnt = min(TILE, NPOINTS - base);
        const float* __restrict__ trow = tid + (size_t)base * NWAVE + w;

        #pragma unroll 8
        for (int i = 0; i < cnt; i++) {
            const float t = trow[(size_t)i * NWAVE];     // coalesced: 128 lanes span one row
            float s, c;
            __sincosf(sdist[i] * kw, &s, &c);            // 2x MUFU
            accC = fmaf(c, t, accC);
            accS = fmaf(s, t, accS);
        }
        __syncthreads();
    }

    g_partialC[blockIdx.x * NWAVE + w] = accC;
    g_partialS[blockIdx.x * NWAVE + w] = accS;
}

__global__ void finalize_kernel(float* __restrict__ out)
{
    __shared__ float sm[NWAVE];
    const int w = threadIdx.x;

    // Fixed-order partial reduction (deterministic).
    float sc = 0.0f, ss = 0.0f;
    #pragma unroll 4
    for (int b = 0; b < NBLOCKS; b++) {
        sc += g_partialC[b * NWAVE + w];
        ss += g_partialS[b * NWAVE + w];
    }
    const float C = sc * (1.0f / (float)NPOINTS);
    const float S = ss * (1.0f / (float)NPOINTS);

    // vals[w, o] = C*cos(o) - S*sin(o), o = linspace(0, 2pi, 50); take max over o.
    float m = -3.402823466e38f;
    #pragma unroll
    for (int i = 0; i < NOFFSETS; i++) {
        const float o = (float)i * (TWO_PI / (float)(NOFFSETS - 1));
        const float v = C * cosf(o) - S * sinf(o);   // precise trig, 6400 evals total
        m = fmaxf(m, v);
    }

    sm[w] = m;
    __syncthreads();

    // Tree-reduce the 128 per-wavelength maxima into the metric sum.
    #pragma unroll
    for (int stride = NWAVE / 2; stride > 0; stride >>= 1) {
        if (w < stride) sm[w] += sm[w + stride];
        __syncthreads();
    }
    if (w == 0) out[0] = -sm[0];
}

extern "C" void kernel_launch(void* const* d_in, const int* in_sizes, int n_in,
                              void* d_out, int out_size)
{
    const float2* xy         = (const float2*)d_in[0];  // [500000, 2]
    const float*  tid        = (const float*) d_in[1];  // [500000, 128]
    const float*  center     = (const float*) d_in[2];  // [2]
    const float*  wavelength = (const float*) d_in[3];  // [128]
    float* out = (float*)d_out;                         // scalar

    accum_kernel<<<NBLOCKS, TPB>>>(xy, tid, center, wavelength);
    finalize_kernel<<<1, NWAVE>>>(out);
}

// round 2
// speedup vs baseline: 2.4917x; 2.4917x over previous
#include <cuda_runtime.h>

// Problem constants (fixed by the reference)
#define NPOINTS     500000
#define NWAVE       128
#define NOFFSETS    50

#define TPB         128     // one thread per wavelength
#define NBLOCKS     1184    // 8 blocks per SM on 148-SM GB300
#define TILE        128     // points per smem tile

#define TWO_PI      6.283185307179586f

// Deterministic reduction scratch. Transposed layout [w][block] so the
// stage-2 per-wavelength reduction reads coalesced.
__device__ float g_partialC[NWAVE * NBLOCKS];
__device__ float g_partialS[NWAVE * NBLOCKS];
__device__ float g_m[NWAVE];

__global__ __launch_bounds__(TPB, 8)
void accum_kernel(const float2* __restrict__ xy,
                  const float*  __restrict__ tid,
                  const float*  __restrict__ center,
                  const float*  __restrict__ wavelength)
{
    __shared__ float sdist[TILE];

    const int w  = threadIdx.x;           // this thread's wavelength column
    const float kw = TWO_PI / wavelength[w];
    const float cx = center[0];
    const float cy = center[1];

    float accC = 0.0f;
    float accS = 0.0f;

    for (int base = blockIdx.x * TILE; base < NPOINTS; base += gridDim.x * TILE) {
        // Phase A: cooperatively compute dist for this tile of points.
        const int p = base + threadIdx.x;
        if (p < NPOINTS) {
            const float2 v = xy[p];
            const float dx = v.x - cx;
            const float dy = v.y - cy;
            sdist[threadIdx.x] = sqrtf(fmaf(dx, dx, dy * dy));
        }
        __syncthreads();

        // Phase B: each thread sweeps the tile's points for its wavelength.
        const int cnt = min(TILE, NPOINTS - base);
        const float* __restrict__ trow = tid + (size_t)base * NWAVE + w;

        #pragma unroll 16
        for (int i = 0; i < cnt; i++) {
            // Streaming load: tid is 256MB read-once, keep it out of L2.
            const float t = __ldcs(trow + (size_t)i * NWAVE);
            float s, c;
            __sincosf(sdist[i] * kw, &s, &c);            // 2x MUFU
            accC = fmaf(c, t, accC);
            accS = fmaf(s, t, accS);
        }
        __syncthreads();
    }

    g_partialC[w * NBLOCKS + blockIdx.x] = accC;
    g_partialS[w * NBLOCKS + blockIdx.x] = accS;
}

// Stage 2: one block per wavelength. 256 threads tree-reduce the 1184
// partials (fixed order -> deterministic), then compute the offset max.
__global__ __launch_bounds__(256)
void reduce_kernel()
{
    __shared__ float sc[256];
    __shared__ float ss[256];

    const int w = blockIdx.x;
    const int t = threadIdx.x;

    const float* __restrict__ pc = g_partialC + (size_t)w * NBLOCKS;
    const float* __restrict__ ps = g_partialS + (size_t)w * NBLOCKS;

    float c = 0.0f, s = 0.0f;
    for (int b = t; b < NBLOCKS; b += 256) {   // coalesced, L2-hot
        c += pc[b];
        s += ps[b];
    }
    sc[t] = c;
    ss[t] = s;
    __syncthreads();

    #pragma unroll
    for (int stride = 128; stride > 0; stride >>= 1) {
        if (t < stride) {
            sc[t] += sc[t + stride];
            ss[t] += ss[t + stride];
        }
        __syncthreads();
    }

    if (t == 0) {
        const float C = sc[0] * (1.0f / (float)NPOINTS);
        const float S = ss[0] * (1.0f / (float)NPOINTS);
        float m = -3.402823466e38f;
        #pragma unroll
        for (int i = 0; i < NOFFSETS; i++) {
            const float o = (float)i * (TWO_PI / (float)(NOFFSETS - 1));
            const float v = C * cosf(o) - S * sinf(o);
            m = fmaxf(m, v);
        }
        g_m[w] = m;
    }
}

// Stage 3: sum the 128 per-wavelength maxima, negate.
__global__ void final_sum_kernel(float* __restrict__ out)
{
    __shared__ float sm[NWAVE];
    const int w = threadIdx.x;
    sm[w] = g_m[w];
    __syncthreads();

    #pragma unroll
    for (int stride = NWAVE / 2; stride > 0; stride >>= 1) {
        if (w < stride) sm[w] += sm[w + stride];
        __syncthreads();
    }
    if (w == 0) out[0] = -sm[0];
}

extern "C" void kernel_launch(void* const* d_in, const int* in_sizes, int n_in,
                              void* d_out, int out_size)
{
    const float2* xy         = (const float2*)d_in[0];  // [500000, 2]
    const float*  tid        = (const float*) d_in[1];  // [500000, 128]
    const float*  center     = (const float*) d_in[2];  // [2]
    const float*  wavelength = (const float*) d_in[3];  // [128]
    float* out = (float*)d_out;                         // scalar

    accum_kernel<<<NBLOCKS, TPB>>>(xy, tid, center, wavelength);
    reduce_kernel<<<NWAVE, 256>>>();
    final_sum_kernel<<<1, NWAVE>>>(out);
}